// round 15
// baseline (speedup 1.0000x reference)
#include <cuda_runtime.h>
#include <cstdint>

// InformPooling, two-pass:
//  Pass 1: 8-row chunk sums of v0/v1/v2 into device scratch (streaming, 128MB read).
//  Pass 2: per query, sum = low-edge rows + interior chunk sums + high-edge rows.
//   value0 [8,16384,128] r=1.0   -> ch [0,128)   chunks: 2048
//   value1 [8, 8192,128] r=0.5   -> ch [128,256) chunks: 1024
//   value2 [8, 4096,256] r=0.25  -> ch [256,512) chunks:  512
// out [8,512,512] fp32.

#define EPS 1e-3f

__device__ float4 g_c0[8 * 2048 * 32];   // 8 MB  [b][chunk][f4of128ch]
__device__ float4 g_c1[8 * 1024 * 32];   // 4 MB
__device__ float4 g_c2[8 *  512 * 64];   // 4 MB

__device__ __forceinline__ void f4add(float4& a, const float4 b) {
    a.x += b.x; a.y += b.y; a.z += b.z; a.w += b.w;
}

// ---------- Pass 1: chunk sums (8 rows per chunk) ----------
__global__ __launch_bounds__(256) void chunk_sum_kernel(
    const float* __restrict__ v0,
    const float* __restrict__ v1,
    const float* __restrict__ v2)
{
    const int z = blockIdx.y;
    const float* src; float4* dst; int nf, nchunk, T;
    if (z == 0)      { src = v0; dst = g_c0; nf = 32; nchunk = 2048; T = 16384; }
    else if (z == 1) { src = v1; dst = g_c1; nf = 32; nchunk = 1024; T = 8192; }
    else             { src = v2; dst = g_c2; nf = 64; nchunk =  512; T = 4096; }

    const int ntask = 8 * nchunk * nf;        // one task = one float4 of one chunk
    const int stride = gridDim.x * blockDim.x;
    for (int i = blockIdx.x * blockDim.x + threadIdx.x; i < ntask; i += stride) {
        const int f4    = i & (nf - 1);
        const int chunk = (i / nf) & (nchunk - 1);
        const int b     = i / (nf * nchunk);
        const float4* p = (const float4*)src + ((size_t)b * T + (size_t)chunk * 8) * nf + f4;
        float4 x0 = p[0];
        float4 x1 = p[nf];
        float4 x2 = p[2 * nf];
        float4 x3 = p[3 * nf];
        float4 x4 = p[4 * nf];
        float4 x5 = p[5 * nf];
        float4 x6 = p[6 * nf];
        float4 x7 = p[7 * nf];
        f4add(x0, x1); f4add(x2, x3); f4add(x4, x5); f4add(x6, x7);
        f4add(x0, x2); f4add(x4, x6); f4add(x0, x4);
        dst[i] = x0;
    }
}

// ---------- Pass 2: per-query pooling via edges + chunks ----------
__global__ __launch_bounds__(128) void inform_pool_kernel(
    const float* __restrict__ v0,
    const float* __restrict__ v1,
    const float* __restrict__ v2,
    const float* __restrict__ start,
    const float* __restrict__ dur,
    float* __restrict__ out)
{
    const int n = blockIdx.x;        // 0..511
    const int b = blockIdx.y;        // 0..7
    const int z = blockIdx.z;        // 0..2
    const int t = threadIdx.x;       // 0..127

    __shared__ float4 red[128];

    const float st = start[b * 512 + n];
    const float du = dur[b * 512 + n];

    float ratio; int T;
    if (z == 0)      { ratio = 1.0f;  T = 16384; }
    else if (z == 1) { ratio = 0.5f;  T = 8192;  }
    else             { ratio = 0.25f; T = 4096;  }

    int s = (int)floorf(st * ratio);
    if (s > T - 1) s = T - 1;
    int e = (int)ceilf((st + du + EPS) * ratio);
    if (e > T - 1) e = T - 1;

    const int rows = e - s;
    const float inv = (rows > 0) ? (1.0f / (float)rows) : 0.0f;

    // chunk range fully inside [s,e)
    int cs = (s + 7) >> 3;
    int ce = e >> 3;

    float* orow = out + ((size_t)b * 512 + n) * 512;

    if (z < 2) {
        const float* src = (z == 0) ? v0 : v1;
        const float4* cb  = ((z == 0) ? g_c0 : g_c1) + (size_t)b * ((z == 0) ? 2048 : 1024) * 32;
        const int coff   = (z == 0) ? 0 : 128;
        const float4* vb = (const float4*)src + (size_t)b * T * 32;
        const int rg = t >> 5;       // 0..3
        const int f4 = t & 31;       // 0..31

        float4 a0 = {0,0,0,0}, a1 = {0,0,0,0};
        if (ce > cs) {
            // low edge rows [s, cs*8)
            for (int r = s + rg; r < (cs << 3); r += 4)
                f4add(a0, vb[(size_t)r * 32 + f4]);
            // high edge rows [ce*8, e)
            for (int r = (ce << 3) + rg; r < e; r += 4)
                f4add(a1, vb[(size_t)r * 32 + f4]);
            // interior chunks [cs, ce)
            int c = cs + rg;
            for (; c + 8 <= ce; c += 8) {
                float4 x0 = cb[(size_t)c * 32 + f4];
                float4 x1 = cb[(size_t)(c + 4) * 32 + f4];
                f4add(a0, x0); f4add(a1, x1);
            }
            for (; c < ce; c += 4)
                f4add(a0, cb[(size_t)c * 32 + f4]);
        } else {
            for (int r = s + rg; r < e; r += 4)
                f4add(a0, vb[(size_t)r * 32 + f4]);
        }
        f4add(a0, a1);

        red[t] = a0;
        __syncthreads();
        if (t < 32) {
            float4 r0 = red[t], r1 = red[t + 32], r2 = red[t + 64], r3 = red[t + 96];
            f4add(r0, r1); f4add(r2, r3); f4add(r0, r2);
            r0.x *= inv; r0.y *= inv; r0.z *= inv; r0.w *= inv;
            ((float4*)(orow + coff))[t] = r0;
        }
    } else {
        const float4* cb = g_c2 + (size_t)b * 512 * 64;
        const float4* vb = (const float4*)v2 + (size_t)b * T * 64;
        const int rg = t >> 6;       // 0..1
        const int f4 = t & 63;       // 0..63

        float4 a0 = {0,0,0,0}, a1 = {0,0,0,0};
        if (ce > cs) {
            for (int r = s + rg; r < (cs << 3); r += 2)
                f4add(a0, vb[(size_t)r * 64 + f4]);
            for (int r = (ce << 3) + rg; r < e; r += 2)
                f4add(a1, vb[(size_t)r * 64 + f4]);
            int c = cs + rg;
            for (; c + 4 <= ce; c += 4) {
                float4 x0 = cb[(size_t)c * 64 + f4];
                float4 x1 = cb[(size_t)(c + 2) * 64 + f4];
                f4add(a0, x0); f4add(a1, x1);
            }
            for (; c < ce; c += 2)
                f4add(a0, cb[(size_t)c * 64 + f4]);
        } else {
            for (int r = s + rg; r < e; r += 2)
                f4add(a0, vb[(size_t)r * 64 + f4]);
        }
        f4add(a0, a1);

        red[t] = a0;
        __syncthreads();
        if (t < 64) {
            float4 r0 = red[t], r1 = red[t + 64];
            f4add(r0, r1);
            r0.x *= inv; r0.y *= inv; r0.z *= inv; r0.w *= inv;
            ((float4*)(orow + 256))[t] = r0;
        }
    }
}

extern "C" void kernel_launch(void* const* d_in, const int* in_sizes, int n_in,
                              void* d_out, int out_size)
{
    const float* v0    = (const float*)d_in[0];
    const float* v1    = (const float*)d_in[1];
    const float* v2    = (const float*)d_in[2];
    const float* start = (const float*)d_in[3];
    const float* dur   = (const float*)d_in[4];
    float* out = (float*)d_out;

    dim3 g1(1024, 3);
    chunk_sum_kernel<<<g1, 256>>>(v0, v1, v2);

    dim3 g2(512, 8, 3);
    inform_pool_kernel<<<g2, 128>>>(v0, v1, v2, start, dur, out);
}